// round 5
// baseline (speedup 1.0000x reference)
#include <cuda_runtime.h>
#include <math.h>

#define NE 480000
#define NN 30000

// ---------------- scratch (device globals; no allocation) ----------------
static __device__ float4 g_geo[NE];          // ux,uy,uz,r
static __device__ float  g_radial[NE*8];
static __device__ float  g_h00[NN*16];
static __device__ float  g_a00[NN*16];
static __device__ float  g_a10[NN*48];
static __device__ float  g_a20[NN*80];
static __device__ float  g_h01[NN*16];
static __device__ float  g_h11[NN*48];
static __device__ float  g_h21[NN*80];
static __device__ float  g_a01[NN*16];
// ---- fp64 backward state ----
static __device__ double g_g0fD[NN*16];
static __device__ double g_ga01D[NN*16];
static __device__ double g_g01D[NN*16];
static __device__ double g_g11D[NN*48];
static __device__ double g_g21D[NN*80];
static __device__ double g_ga00D[NN*16];
static __device__ double g_ga10D[NN*48];
static __device__ double g_ga20D[NN*80];
static __device__ double g_gshD[NE*8];       // [0..2]=dsh1, [3..7]=dsh2
static __device__ double g_gradD[NE*8];      // dE/dradial
static __device__ double g_energy;
// ---- CSR for reference-order force accumulation ----
static __device__ int    g_cntR[NN], g_cntC[NN];
static __device__ int    g_offR[NN], g_offC[NN];
static __device__ int    g_curR[NN], g_curC[NN];
static __device__ int    g_lstR[NE], g_lstC[NE];
static __device__ float  g_gv[NE*3];         // per-edge dE/d(edge_vec), fp32

__device__ __forceinline__ void sh_basis_f(float ux, float uy, float uz,
                                           float* s1, float* s2) {
    const float SQ3 = 1.7320508075688772f;
    const float S15 = 3.872983346207417f;
    const float S5  = 2.23606797749979f;
    s1[0] = SQ3 * ux; s1[1] = SQ3 * uy; s1[2] = SQ3 * uz;
    s2[0] = S15 * ux * uy;
    s2[1] = S15 * uy * uz;
    s2[2] = 0.5f * S5 * (3.f * uz * uz - 1.f);
    s2[3] = S15 * ux * uz;
    s2[4] = 0.5f * S15 * (ux * ux - uy * uy);
}

__device__ __forceinline__ void sh_basis_d(double ux, double uy, double uz,
                                           double* s1, double* s2) {
    const double SQ3 = 1.7320508075688772;
    const double S15 = 3.872983346207417;
    const double S5  = 2.23606797749979;
    s1[0] = SQ3 * ux; s1[1] = SQ3 * uy; s1[2] = SQ3 * uz;
    s2[0] = S15 * ux * uy;
    s2[1] = S15 * uy * uz;
    s2[2] = 0.5 * S5 * (3.0 * uz * uz - 1.0);
    s2[3] = S15 * ux * uz;
    s2[4] = 0.5 * S15 * (ux * ux - uy * uy);
}

// ---------------- forward: geometry ----------------
__global__ void k_geom_fwd(const float* __restrict__ pos, const int* __restrict__ ei) {
    int e = blockIdx.x * blockDim.x + threadIdx.x;
    if (e >= NE) return;
    int rw = ei[e], cl = ei[NE + e];
    float vx = pos[3*rw+0] - pos[3*cl+0];
    float vy = pos[3*rw+1] - pos[3*cl+1];
    float vz = pos[3*rw+2] - pos[3*cl+2];
    float r = sqrtf(vx*vx + vy*vy + vz*vz + 1e-12f);
    float inv = 1.f / r;
    g_geo[e] = make_float4(vx*inv, vy*inv, vz*inv, r);
    const float A = 0.6324555320336759f;       // sqrt(2/5)
    const float KPI = 0.6283185307179586f;     // pi/5
    #pragma unroll
    for (int n = 0; n < 8; n++) {
        float kn = (float)(n + 1) * KPI;
        g_radial[e*8 + n] = A * sinf(kn * r) * inv;
    }
    // CSR counting
    atomicAdd(&g_cntR[rw], 1);
    atomicAdd(&g_cntC[cl], 1);
}

// ---------------- CSR: exclusive scan (single block, 1024 threads) ----------------
__global__ void k_scan(const int* __restrict__ cnt, int* __restrict__ off) {
    __shared__ int part[1024];
    const int CH = 32;                    // 1024*32 = 32768 >= NN
    int t = threadIdx.x;
    int base = t * CH;
    int s = 0;
    for (int i = 0; i < CH; i++) {
        int idx = base + i;
        if (idx < NN) s += cnt[idx];
    }
    part[t] = s;
    __syncthreads();
    for (int o = 1; o < 1024; o <<= 1) {
        int v = (t >= o) ? part[t - o] : 0;
        __syncthreads();
        part[t] += v;
        __syncthreads();
    }
    int run = (t > 0) ? part[t - 1] : 0;
    for (int i = 0; i < CH; i++) {
        int idx = base + i;
        if (idx < NN) { off[idx] = run; run += cnt[idx]; }
    }
}

// ---------------- CSR: fill (unordered) ----------------
__global__ void k_fill(const int* __restrict__ ei) {
    int e = blockIdx.x * blockDim.x + threadIdx.x;
    if (e >= NE) return;
    int rw = ei[e], cl = ei[NE + e];
    int p1 = g_offR[rw] + atomicAdd(&g_curR[rw], 1);
    g_lstR[p1] = e;
    int p2 = g_offC[cl] + atomicAdd(&g_curC[cl], 1);
    g_lstC[p2] = e;
}

// ---------------- CSR: sort each bucket ascending (insertion sort) ----------------
__global__ void k_sort() {
    int n = blockIdx.x * blockDim.x + threadIdx.x;
    if (n >= NN) return;
    {
        int lo = g_offR[n], hi = lo + g_cntR[n];
        for (int i = lo + 1; i < hi; i++) {
            int key = g_lstR[i], j = i - 1;
            while (j >= lo && g_lstR[j] > key) { g_lstR[j+1] = g_lstR[j]; j--; }
            g_lstR[j+1] = key;
        }
    }
    {
        int lo = g_offC[n], hi = lo + g_cntC[n];
        for (int i = lo + 1; i < hi; i++) {
            int key = g_lstC[i], j = i - 1;
            while (j >= lo && g_lstC[j] > key) { g_lstC[j+1] = g_lstC[j]; j--; }
            g_lstC[j+1] = key;
        }
    }
}

// ---------------- forward: h0 init = emb[z] @ W_init ----------------
__global__ void k_node_init(const float* __restrict__ emb, const int* __restrict__ z,
                            const float* __restrict__ W_init) {
    __shared__ float Ws[256];
    for (int i = threadIdx.x; i < 256; i += blockDim.x) Ws[i] = W_init[i];
    __syncthreads();
    int t = blockIdx.x * blockDim.x + threadIdx.x;
    if (t >= NN * 16) return;
    int n = t >> 4, d = t & 15;
    const float* er = emb + z[n] * 16;
    float acc = 0.f;
    #pragma unroll
    for (int k = 0; k < 16; k++) acc += er[k] * Ws[k*16 + d];
    g_h00[t] = acc;
}

// ---------------- forward: block0 edge (paths 0,1,2) ----------------
__global__ void k_edge_fwd0(const int* __restrict__ ei,
                            const float* __restrict__ Wr, const float* __restrict__ br) {
    __shared__ float Wrs[640], brs[80];
    for (int i = threadIdx.x; i < 640; i += blockDim.x) Wrs[i] = Wr[i];
    for (int i = threadIdx.x; i < 80;  i += blockDim.x) brs[i] = br[i];
    __syncthreads();
    long t = (long)blockIdx.x * blockDim.x + threadIdx.x;
    int e = (int)(t >> 4), c = (int)(t & 15);
    int rw = ei[e], cl = ei[NE + e];
    float4 g = g_geo[e];
    float s1[3], s2[5];
    sh_basis_f(g.x, g.y, g.z, s1, s2);
    float rad[8];
    #pragma unroll
    for (int n = 0; n < 8; n++) rad[n] = g_radial[e*8 + n];
    float w0 = brs[c], w1 = brs[16 + c], w2 = brs[32 + c];
    #pragma unroll
    for (int n = 0; n < 8; n++) {
        w0 += rad[n] * Wrs[n*80 + c];
        w1 += rad[n] * Wrs[n*80 + 16 + c];
        w2 += rad[n] * Wrs[n*80 + 32 + c];
    }
    float h0c = g_h00[cl*16 + c];
    atomicAdd(&g_a00[rw*16 + c], w0 * h0c);
    float f1 = w1 * h0c, f2 = w2 * h0c;
    #pragma unroll
    for (int m = 0; m < 3; m++) atomicAdd(&g_a10[rw*48 + c*3 + m], f1 * s1[m]);
    #pragma unroll
    for (int m = 0; m < 5; m++) atomicAdd(&g_a20[rw*80 + c*5 + m], f2 * s2[m]);
}

// ---------------- forward: block0 node update ----------------
__global__ void k_node_upd0(const float* __restrict__ Wout) {
    __shared__ float W0s[256], W1s[256], W2s[256];
    for (int i = threadIdx.x; i < 256; i += blockDim.x) {
        W0s[i] = Wout[i]; W1s[i] = Wout[256 + i]; W2s[i] = Wout[512 + i];
    }
    __syncthreads();
    int t = blockIdx.x * blockDim.x + threadIdx.x;
    if (t >= NN * 16) return;
    int n = t >> 4, d = t & 15;
    float acc0 = g_h00[n*16 + d];
    float a1[3] = {0,0,0}, a2[5] = {0,0,0,0,0};
    #pragma unroll
    for (int cc = 0; cc < 16; cc++) {
        acc0 += g_a00[n*16 + cc] * W0s[cc*16 + d];
        float w1 = W1s[cc*16 + d];
        #pragma unroll
        for (int m = 0; m < 3; m++) a1[m] += g_a10[n*48 + cc*3 + m] * w1;
        float w2 = W2s[cc*16 + d];
        #pragma unroll
        for (int m = 0; m < 5; m++) a2[m] += g_a20[n*80 + cc*5 + m] * w2;
    }
    g_h01[n*16 + d] = acc0;
    #pragma unroll
    for (int m = 0; m < 3; m++) g_h11[n*48 + d*3 + m] = a1[m];
    #pragma unroll
    for (int m = 0; m < 5; m++) g_h21[n*80 + d*5 + m] = a2[m];
}

// ---------------- forward: block1 edge (paths 0,3,4; m0 only) ----------------
__global__ void k_edge_fwd1(const int* __restrict__ ei,
                            const float* __restrict__ Wr, const float* __restrict__ br) {
    __shared__ float Wrs[640], brs[80];
    for (int i = threadIdx.x; i < 640; i += blockDim.x) Wrs[i] = Wr[i];
    for (int i = threadIdx.x; i < 80;  i += blockDim.x) brs[i] = br[i];
    __syncthreads();
    long t = (long)blockIdx.x * blockDim.x + threadIdx.x;
    int e = (int)(t >> 4), c = (int)(t & 15);
    int rw = ei[e], cl = ei[NE + e];
    float4 g = g_geo[e];
    float s1[3], s2[5];
    sh_basis_f(g.x, g.y, g.z, s1, s2);
    float rad[8];
    #pragma unroll
    for (int n = 0; n < 8; n++) rad[n] = g_radial[e*8 + n];
    float w0 = brs[c], w3 = brs[48 + c], w4 = brs[64 + c];
    #pragma unroll
    for (int n = 0; n < 8; n++) {
        w0 += rad[n] * Wrs[n*80 + c];
        w3 += rad[n] * Wrs[n*80 + 48 + c];
        w4 += rad[n] * Wrs[n*80 + 64 + c];
    }
    float h0c = g_h01[cl*16 + c];
    float d1 = 0.f, d2 = 0.f;
    #pragma unroll
    for (int m = 0; m < 3; m++) d1 += g_h11[cl*48 + c*3 + m] * s1[m];
    #pragma unroll
    for (int m = 0; m < 5; m++) d2 += g_h21[cl*80 + c*5 + m] * s2[m];
    atomicAdd(&g_a01[rw*16 + c], w0 * h0c + w3 * d1 + w4 * d2);
}

// ---------------- readout: energy + dE/dh0_final (fp64 cotangent) ----------------
__global__ void k_readout(const float* __restrict__ W10, const float* __restrict__ W_read,
                          const float* __restrict__ W1, const float* __restrict__ b1,
                          const float* __restrict__ W2, const float* __restrict__ b2) {
    __shared__ float W10s[256], WRs[256], W1s[256], W2s[16], b1s[16];
    __shared__ float b2s;
    __shared__ double esum[256];
    for (int i = threadIdx.x; i < 256; i += blockDim.x) {
        W10s[i] = W10[i]; WRs[i] = W_read[i]; W1s[i] = W1[i];
    }
    if (threadIdx.x < 16) { W2s[threadIdx.x] = W2[threadIdx.x]; b1s[threadIdx.x] = b1[threadIdx.x]; }
    if (threadIdx.x == 0) b2s = b2[0];
    __syncthreads();
    int n = blockIdx.x * blockDim.x + threadIdx.x;
    double site = 0.0;
    if (n < NN) {
        float h0f[16];
        #pragma unroll
        for (int d = 0; d < 16; d++) h0f[d] = g_h01[n*16 + d];
        #pragma unroll
        for (int cc = 0; cc < 16; cc++) {
            float a = g_a01[n*16 + cc];
            #pragma unroll
            for (int d = 0; d < 16; d++) h0f[d] += a * W10s[cc*16 + d];
        }
        float invv[16];
        #pragma unroll
        for (int d = 0; d < 16; d++) {
            float acc = 0.f;
            #pragma unroll
            for (int cc = 0; cc < 16; cc++) acc += h0f[cc] * WRs[cc*16 + d];
            invv[d] = acc;
        }
        double sp[16];
        float sacc = b2s;
        #pragma unroll
        for (int k = 0; k < 16; k++) {
            float tt = b1s[k];
            #pragma unroll
            for (int d = 0; d < 16; d++) tt += invv[d] * W1s[d*16 + k];
            float sg = 1.f / (1.f + expf(-tt));
            sacc += tt * sg * W2s[k];
            double ttd = (double)tt, sgd = 1.0 / (1.0 + exp(-ttd));
            sp[k] = sgd * (1.0 + ttd * (1.0 - sgd)) * (double)W2s[k];
        }
        site = (double)sacc;
        double q[16];
        #pragma unroll
        for (int d = 0; d < 16; d++) {
            double acc = 0.0;
            #pragma unroll
            for (int k = 0; k < 16; k++) acc += (double)W1s[d*16 + k] * sp[k];
            q[d] = acc;
        }
        #pragma unroll
        for (int cc = 0; cc < 16; cc++) {
            double acc = 0.0;
            #pragma unroll
            for (int d = 0; d < 16; d++) acc += (double)WRs[cc*16 + d] * q[d];
            g_g0fD[n*16 + cc] = acc;
        }
    }
    esum[threadIdx.x] = site;
    __syncthreads();
    for (int s = 128; s > 0; s >>= 1) {
        if (threadIdx.x < s) esum[threadIdx.x] += esum[threadIdx.x + s];
        __syncthreads();
    }
    if (threadIdx.x == 0) atomicAdd(&g_energy, esum[0]);
}

// ---------------- backward: node-level for block1 (fp64) ----------------
__global__ void k_bwd_node1(const float* __restrict__ W10) {
    __shared__ float Ws[256];
    for (int i = threadIdx.x; i < 256; i += blockDim.x) Ws[i] = W10[i];
    __syncthreads();
    int t = blockIdx.x * blockDim.x + threadIdx.x;
    if (t >= NN * 16) return;
    int n = t >> 4, c = t & 15;
    double acc = 0.0;
    #pragma unroll
    for (int d = 0; d < 16; d++) acc += g_g0fD[n*16 + d] * (double)Ws[c*16 + d];
    g_ga01D[t] = acc;
    g_g01D[t] = g_g0fD[t];
}

// ---------------- backward: block1 edge (fp64) ----------------
__global__ void k_bwd_edge1(const int* __restrict__ ei,
                            const float* __restrict__ Wr, const float* __restrict__ br) {
    __shared__ float Wrs[640], brs[80];
    for (int i = threadIdx.x; i < 640; i += blockDim.x) Wrs[i] = Wr[i];
    for (int i = threadIdx.x; i < 80;  i += blockDim.x) brs[i] = br[i];
    __syncthreads();
    long t = (long)blockIdx.x * blockDim.x + threadIdx.x;
    int e = (int)(t >> 4), c = (int)(t & 15);
    int rw = ei[e], cl = ei[NE + e];
    float4 g = g_geo[e];
    double s1[3], s2[5];
    sh_basis_d((double)g.x, (double)g.y, (double)g.z, s1, s2);
    double w0 = brs[c], w3 = brs[48 + c], w4 = brs[64 + c];
    #pragma unroll
    for (int n = 0; n < 8; n++) {
        double rn = (double)g_radial[e*8 + n];
        w0 += rn * (double)Wrs[n*80 + c];
        w3 += rn * (double)Wrs[n*80 + 48 + c];
        w4 += rn * (double)Wrs[n*80 + 64 + c];
    }
    double gm0 = g_ga01D[rw*16 + c];
    double h0c = (double)g_h01[cl*16 + c];
    double h1c[3], h2c[5];
    #pragma unroll
    for (int m = 0; m < 3; m++) h1c[m] = (double)g_h11[cl*48 + c*3 + m];
    #pragma unroll
    for (int m = 0; m < 5; m++) h2c[m] = (double)g_h21[cl*80 + c*5 + m];

    atomicAdd(&g_g01D[cl*16 + c], gm0 * w0);
    double gw3 = gm0 * w3, gw4 = gm0 * w4;
    #pragma unroll
    for (int m = 0; m < 3; m++) atomicAdd(&g_g11D[cl*48 + c*3 + m], gw3 * s1[m]);
    #pragma unroll
    for (int m = 0; m < 5; m++) atomicAdd(&g_g21D[cl*80 + c*5 + m], gw4 * s2[m]);

    double red[16];
    #pragma unroll
    for (int m = 0; m < 3; m++) red[m] = gw3 * h1c[m];
    #pragma unroll
    for (int m = 0; m < 5; m++) red[3 + m] = gw4 * h2c[m];
    double d1 = 0.0, d2 = 0.0;
    #pragma unroll
    for (int m = 0; m < 3; m++) d1 += h1c[m] * s1[m];
    #pragma unroll
    for (int m = 0; m < 5; m++) d2 += h2c[m] * s2[m];
    double dw0 = gm0 * h0c, dw3 = gm0 * d1, dw4 = gm0 * d2;
    #pragma unroll
    for (int n = 0; n < 8; n++)
        red[8 + n] = dw0 * (double)Wrs[n*80 + c] + dw3 * (double)Wrs[n*80 + 48 + c]
                   + dw4 * (double)Wrs[n*80 + 64 + c];

    #pragma unroll
    for (int off = 8; off > 0; off >>= 1) {
        #pragma unroll
        for (int i = 0; i < 16; i++)
            red[i] += __shfl_xor_sync(0xffffffffu, red[i], off, 16);
    }
    if (c == 0) {
        #pragma unroll
        for (int i = 0; i < 8; i++) g_gshD[e*8 + i] = red[i];
        #pragma unroll
        for (int n = 0; n < 8; n++) g_gradD[e*8 + n] = red[8 + n];
    }
}

// ---------------- backward: node-level for block0 (fp64) ----------------
__global__ void k_bwd_node0(const float* __restrict__ Wout) {
    __shared__ float W0s[256], W1s[256], W2s[256];
    for (int i = threadIdx.x; i < 256; i += blockDim.x) {
        W0s[i] = Wout[i]; W1s[i] = Wout[256 + i]; W2s[i] = Wout[512 + i];
    }
    __syncthreads();
    int t = blockIdx.x * blockDim.x + threadIdx.x;
    if (t >= NN * 16) return;
    int n = t >> 4, c = t & 15;
    double a0 = 0.0, a1[3] = {0,0,0}, a2[5] = {0,0,0,0,0};
    #pragma unroll
    for (int d = 0; d < 16; d++) {
        a0 += g_g01D[n*16 + d] * (double)W0s[c*16 + d];
        double w1 = (double)W1s[c*16 + d];
        #pragma unroll
        for (int m = 0; m < 3; m++) a1[m] += g_g11D[n*48 + d*3 + m] * w1;
        double w2 = (double)W2s[c*16 + d];
        #pragma unroll
        for (int m = 0; m < 5; m++) a2[m] += g_g21D[n*80 + d*5 + m] * w2;
    }
    g_ga00D[n*16 + c] = a0;
    #pragma unroll
    for (int m = 0; m < 3; m++) g_ga10D[n*48 + c*3 + m] = a1[m];
    #pragma unroll
    for (int m = 0; m < 5; m++) g_ga20D[n*80 + c*5 + m] = a2[m];
}

// ---------------- backward: block0 edge (fp64) ----------------
__global__ void k_bwd_edge0(const int* __restrict__ ei,
                            const float* __restrict__ Wr, const float* __restrict__ br) {
    __shared__ float Wrs[640], brs[80];
    for (int i = threadIdx.x; i < 640; i += blockDim.x) Wrs[i] = Wr[i];
    for (int i = threadIdx.x; i < 80;  i += blockDim.x) brs[i] = br[i];
    __syncthreads();
    long t = (long)blockIdx.x * blockDim.x + threadIdx.x;
    int e = (int)(t >> 4), c = (int)(t & 15);
    int rw = ei[e], cl = ei[NE + e];
    float4 g = g_geo[e];
    double s1[3], s2[5];
    sh_basis_d((double)g.x, (double)g.y, (double)g.z, s1, s2);
    double w0 = brs[c], w1 = brs[16 + c], w2 = brs[32 + c];
    #pragma unroll
    for (int n = 0; n < 8; n++) {
        double rn = (double)g_radial[e*8 + n];
        w0 += rn * (double)Wrs[n*80 + c];
        w1 += rn * (double)Wrs[n*80 + 16 + c];
        w2 += rn * (double)Wrs[n*80 + 32 + c];
    }
    double gm0 = g_ga00D[rw*16 + c];
    double gm1[3], gm2[5];
    #pragma unroll
    for (int m = 0; m < 3; m++) gm1[m] = g_ga10D[rw*48 + c*3 + m];
    #pragma unroll
    for (int m = 0; m < 5; m++) gm2[m] = g_ga20D[rw*80 + c*5 + m];
    double h0c = (double)g_h00[cl*16 + c];
    double d1 = 0.0, d2 = 0.0;
    #pragma unroll
    for (int m = 0; m < 3; m++) d1 += gm1[m] * s1[m];
    #pragma unroll
    for (int m = 0; m < 5; m++) d2 += gm2[m] * s2[m];

    double red[16];
    double w1h = w1 * h0c, w2h = w2 * h0c;
    #pragma unroll
    for (int m = 0; m < 3; m++) red[m] = gm1[m] * w1h;
    #pragma unroll
    for (int m = 0; m < 5; m++) red[3 + m] = gm2[m] * w2h;
    double dw0 = gm0 * h0c, dw1 = h0c * d1, dw2 = h0c * d2;
    #pragma unroll
    for (int n = 0; n < 8; n++)
        red[8 + n] = dw0 * (double)Wrs[n*80 + c] + dw1 * (double)Wrs[n*80 + 16 + c]
                   + dw2 * (double)Wrs[n*80 + 32 + c];

    #pragma unroll
    for (int off = 8; off > 0; off >>= 1) {
        #pragma unroll
        for (int i = 0; i < 16; i++)
            red[i] += __shfl_xor_sync(0xffffffffu, red[i], off, 16);
    }
    if (c == 0) {
        #pragma unroll
        for (int i = 0; i < 8; i++) g_gshD[e*8 + i] += red[i];
        #pragma unroll
        for (int n = 0; n < 8; n++) g_gradD[e*8 + n] += red[8 + n];
    }
}

// ---------------- per-edge gv = dE/d(edge_vec), fp32, monsters included ----------------
__global__ void k_gv() {
    int e = blockIdx.x * blockDim.x + threadIdx.x;
    if (e >= NE) return;
    float4 g = g_geo[e];
    double ux = g.x, uy = g.y, uz = g.z, r = g.w;
    double inv = 1.0 / r;
    double gs[8], gd[8];
    #pragma unroll
    for (int i = 0; i < 8; i++) { gs[i] = g_gshD[e*8 + i]; gd[i] = g_gradD[e*8 + i]; }
    const double SQ3 = 1.7320508075688772;
    const double S15 = 3.872983346207417;
    const double S5  = 2.23606797749979;
    const double A   = 0.6324555320336759;
    const double KPI = 0.6283185307179586;
    double gux = SQ3 * gs[0] + S15 * (uy * gs[3] + uz * gs[6] + ux * gs[7]);
    double guy = SQ3 * gs[1] + S15 * (ux * gs[3] + uz * gs[4] - uy * gs[7]);
    double guz = SQ3 * gs[2] + S15 * (uy * gs[4] + ux * gs[6]) + 3.0 * S5 * uz * gs[5];
    double gr = 0.0;
    #pragma unroll
    for (int n = 0; n < 8; n++) {
        double kn = (double)(n + 1) * KPI;
        gr += gd[n] * (A * kn * cos(kn * r) - (double)g_radial[e*8 + n]) * inv;
    }
    double guu = gux * ux + guy * uy + guz * uz;
    g_gv[e*3 + 0] = (float)(gr * ux + (gux - guu * ux) * inv);
    g_gv[e*3 + 1] = (float)(gr * uy + (guy - guu * uy) * inv);
    g_gv[e*3 + 2] = (float)(gr * uz + (guz - guu * uz) * inv);
}

// ---------------- forces: emulate XLA's two sequential fp32 scatter-adds ----------------
__global__ void k_forces(float* __restrict__ out) {
    int n = blockIdx.x * blockDim.x + threadIdx.x;
    if (n >= NN) return;
    if (n == 0) out[0] = (float)g_energy;
    // A1 = scatter_add(+gv, row)[n]  (ascending edge order, fp32 sequential)
    float a1x = 0.f, a1y = 0.f, a1z = 0.f;
    {
        int lo = g_offR[n], hi = lo + g_cntR[n];
        for (int i = lo; i < hi; i++) {
            int e = g_lstR[i];
            a1x += g_gv[e*3 + 0];
            a1y += g_gv[e*3 + 1];
            a1z += g_gv[e*3 + 2];
        }
    }
    // A2 = scatter_add(-gv, col)[n]
    float a2x = 0.f, a2y = 0.f, a2z = 0.f;
    {
        int lo = g_offC[n], hi = lo + g_cntC[n];
        for (int i = lo; i < hi; i++) {
            int e = g_lstC[i];
            a2x += -g_gv[e*3 + 0];
            a2y += -g_gv[e*3 + 1];
            a2z += -g_gv[e*3 + 2];
        }
    }
    // dpos = A1 + A2 ; forces = -dpos
    out[1 + n*3 + 0] = -(a1x + a2x);
    out[1 + n*3 + 1] = -(a1y + a2y);
    out[1 + n*3 + 2] = -(a1z + a2z);
}

// ---------------- host ----------------
extern "C" void kernel_launch(void* const* d_in, const int* in_sizes, int n_in,
                              void* d_out, int out_size) {
    const float* pos    = (const float*)d_in[0];
    const int*   z      = (const int*)  d_in[1];
    const int*   ei     = (const int*)  d_in[2];
    const float* emb    = (const float*)d_in[3];
    const float* W_init = (const float*)d_in[4];
    const float* Wr     = (const float*)d_in[5];
    const float* br     = (const float*)d_in[6];
    const float* W_out  = (const float*)d_in[7];
    const float* W_read = (const float*)d_in[8];
    const float* W1     = (const float*)d_in[9];
    const float* b1     = (const float*)d_in[10];
    const float* W2     = (const float*)d_in[11];
    const float* b2     = (const float*)d_in[12];
    float* out = (float*)d_out;

    void *pa00, *pa10, *pa20, *pa01, *pg11, *pg21, *pen;
    void *pcr, *pcc, *pur, *puc, *por, *poc;
    cudaGetSymbolAddress(&pa00, g_a00);
    cudaGetSymbolAddress(&pa10, g_a10);
    cudaGetSymbolAddress(&pa20, g_a20);
    cudaGetSymbolAddress(&pa01, g_a01);
    cudaGetSymbolAddress(&pg11, g_g11D);
    cudaGetSymbolAddress(&pg21, g_g21D);
    cudaGetSymbolAddress(&pen,  g_energy);
    cudaGetSymbolAddress(&pcr,  g_cntR);
    cudaGetSymbolAddress(&pcc,  g_cntC);
    cudaGetSymbolAddress(&pur,  g_curR);
    cudaGetSymbolAddress(&puc,  g_curC);
    cudaGetSymbolAddress(&por,  g_offR);
    cudaGetSymbolAddress(&poc,  g_offC);

    cudaMemsetAsync(pa00, 0, sizeof(float)  * NN * 16, 0);
    cudaMemsetAsync(pa10, 0, sizeof(float)  * NN * 48, 0);
    cudaMemsetAsync(pa20, 0, sizeof(float)  * NN * 80, 0);
    cudaMemsetAsync(pa01, 0, sizeof(float)  * NN * 16, 0);
    cudaMemsetAsync(pg11, 0, sizeof(double) * NN * 48, 0);
    cudaMemsetAsync(pg21, 0, sizeof(double) * NN * 80, 0);
    cudaMemsetAsync(pen,  0, sizeof(double), 0);
    cudaMemsetAsync(pcr,  0, sizeof(int) * NN, 0);
    cudaMemsetAsync(pcc,  0, sizeof(int) * NN, 0);
    cudaMemsetAsync(pur,  0, sizeof(int) * NN, 0);
    cudaMemsetAsync(puc,  0, sizeof(int) * NN, 0);

    const int TPB = 256;
    k_geom_fwd <<<NE / TPB, TPB>>>(pos, ei);
    k_scan     <<<1, 1024>>>((const int*)pcr, (int*)por);
    k_scan     <<<1, 1024>>>((const int*)pcc, (int*)poc);
    k_fill     <<<NE / TPB, TPB>>>(ei);
    k_sort     <<<(NN + TPB - 1) / TPB, TPB>>>();
    k_node_init<<<NN * 16 / TPB, TPB>>>(emb, z, W_init);
    k_edge_fwd0<<<NE * 16 / TPB, TPB>>>(ei, Wr, br);
    k_node_upd0<<<NN * 16 / TPB, TPB>>>(W_out);
    k_edge_fwd1<<<NE * 16 / TPB, TPB>>>(ei, Wr + 640, br + 80);
    k_readout  <<<(NN + TPB - 1) / TPB, TPB>>>(W_out + 768, W_read, W1, b1, W2, b2);
    k_bwd_node1<<<NN * 16 / TPB, TPB>>>(W_out + 768);
    k_bwd_edge1<<<NE * 16 / TPB, TPB>>>(ei, Wr + 640, br + 80);
    k_bwd_node0<<<NN * 16 / TPB, TPB>>>(W_out);
    k_bwd_edge0<<<NE * 16 / TPB, TPB>>>(ei, Wr, br);
    k_gv       <<<NE / TPB, TPB>>>();
    k_forces   <<<(NN + TPB - 1) / TPB, TPB>>>(out);
}

// round 6
// speedup vs baseline: 7.9255x; 7.9255x over previous
#include <cuda_runtime.h>
#include <math.h>

#define NE 480000
#define NN 30000

// ---------------- scratch (device globals; no allocation) ----------------
static __device__ float4 g_geo[NE];          // ux,uy,uz,r
static __device__ float  g_radial[NE*8];
static __device__ float  g_h00[NN*16];
static __device__ float  g_a00[NN*16];
static __device__ float  g_a10[NN*48];
static __device__ float  g_a20[NN*80];
static __device__ float  g_h01[NN*16];
static __device__ float  g_h11[NN*48];
static __device__ float  g_h21[NN*80];
static __device__ float  g_a01[NN*16];
static __device__ float  g_g0f[NN*16];
static __device__ float  g_ga01[NN*16];
static __device__ float  g_g01[NN*16];
static __device__ float  g_g11[NN*48];
static __device__ float  g_g21[NN*80];
static __device__ float  g_ga00[NN*16];
static __device__ float  g_ga10[NN*48];
static __device__ float  g_ga20[NN*80];
static __device__ float  g_gsh[NE*8];        // block1 edge: [0..2]=dsh1, [3..7]=dsh2
static __device__ float  g_grad[NE*8];       // block1 edge: dE/dradial
static __device__ double g_energy;
// ---- CSR for reference-order force accumulation ----
static __device__ int    g_cntR[NN], g_cntC[NN];
static __device__ int    g_offR[NN], g_offC[NN];
static __device__ int    g_curR[NN], g_curC[NN];
static __device__ int    g_lstR[NE], g_lstC[NE];
static __device__ float  g_gv[NE*3];         // per-edge dE/d(edge_vec), fp32

__device__ __forceinline__ void sh_basis_f(float ux, float uy, float uz,
                                           float* s1, float* s2) {
    const float SQ3 = 1.7320508075688772f;
    const float S15 = 3.872983346207417f;
    const float S5  = 2.23606797749979f;
    s1[0] = SQ3 * ux; s1[1] = SQ3 * uy; s1[2] = SQ3 * uz;
    s2[0] = S15 * ux * uy;
    s2[1] = S15 * uy * uz;
    s2[2] = 0.5f * S5 * (3.f * uz * uz - 1.f);
    s2[3] = S15 * ux * uz;
    s2[4] = 0.5f * S15 * (ux * ux - uy * uy);
}

// ---------------- forward: geometry (+ CSR counting) ----------------
__global__ void k_geom_fwd(const float* __restrict__ pos, const int* __restrict__ ei) {
    int e = blockIdx.x * blockDim.x + threadIdx.x;
    if (e >= NE) return;
    int rw = ei[e], cl = ei[NE + e];
    float vx = pos[3*rw+0] - pos[3*cl+0];
    float vy = pos[3*rw+1] - pos[3*cl+1];
    float vz = pos[3*rw+2] - pos[3*cl+2];
    float r = sqrtf(vx*vx + vy*vy + vz*vz + 1e-12f);
    float inv = 1.f / r;
    g_geo[e] = make_float4(vx*inv, vy*inv, vz*inv, r);
    const float A = 0.6324555320336759f;       // sqrt(2/5)
    const float KPI = 0.6283185307179586f;     // pi/5
    #pragma unroll
    for (int n = 0; n < 8; n++) {
        float kn = (float)(n + 1) * KPI;
        g_radial[e*8 + n] = A * sinf(kn * r) * inv;
    }
    atomicAdd(&g_cntR[rw], 1);
    atomicAdd(&g_cntC[cl], 1);
}

// ---------------- CSR: exclusive scan (single block, 1024 threads) ----------------
__global__ void k_scan(const int* __restrict__ cnt, int* __restrict__ off) {
    __shared__ int part[1024];
    const int CH = 32;                    // 1024*32 = 32768 >= NN
    int t = threadIdx.x;
    int base = t * CH;
    int s = 0;
    for (int i = 0; i < CH; i++) {
        int idx = base + i;
        if (idx < NN) s += cnt[idx];
    }
    part[t] = s;
    __syncthreads();
    for (int o = 1; o < 1024; o <<= 1) {
        int v = (t >= o) ? part[t - o] : 0;
        __syncthreads();
        part[t] += v;
        __syncthreads();
    }
    int run = (t > 0) ? part[t - 1] : 0;
    for (int i = 0; i < CH; i++) {
        int idx = base + i;
        if (idx < NN) { off[idx] = run; run += cnt[idx]; }
    }
}

// ---------------- CSR: fill (unordered) ----------------
__global__ void k_fill(const int* __restrict__ ei) {
    int e = blockIdx.x * blockDim.x + threadIdx.x;
    if (e >= NE) return;
    int rw = ei[e], cl = ei[NE + e];
    int p1 = g_offR[rw] + atomicAdd(&g_curR[rw], 1);
    g_lstR[p1] = e;
    int p2 = g_offC[cl] + atomicAdd(&g_curC[cl], 1);
    g_lstC[p2] = e;
}

// ---------------- CSR: sort each bucket ascending ----------------
__global__ void k_sort() {
    int n = blockIdx.x * blockDim.x + threadIdx.x;
    if (n >= NN) return;
    {
        int lo = g_offR[n], hi = lo + g_cntR[n];
        for (int i = lo + 1; i < hi; i++) {
            int key = g_lstR[i], j = i - 1;
            while (j >= lo && g_lstR[j] > key) { g_lstR[j+1] = g_lstR[j]; j--; }
            g_lstR[j+1] = key;
        }
    }
    {
        int lo = g_offC[n], hi = lo + g_cntC[n];
        for (int i = lo + 1; i < hi; i++) {
            int key = g_lstC[i], j = i - 1;
            while (j >= lo && g_lstC[j] > key) { g_lstC[j+1] = g_lstC[j]; j--; }
            g_lstC[j+1] = key;
        }
    }
}

// ---------------- forward: h0 init = emb[z] @ W_init ----------------
__global__ void k_node_init(const float* __restrict__ emb, const int* __restrict__ z,
                            const float* __restrict__ W_init) {
    __shared__ float Ws[256];
    for (int i = threadIdx.x; i < 256; i += blockDim.x) Ws[i] = W_init[i];
    __syncthreads();
    int t = blockIdx.x * blockDim.x + threadIdx.x;
    if (t >= NN * 16) return;
    int n = t >> 4, d = t & 15;
    const float* er = emb + z[n] * 16;
    float acc = 0.f;
    #pragma unroll
    for (int k = 0; k < 16; k++) acc += er[k] * Ws[k*16 + d];
    g_h00[t] = acc;
}

// ---------------- forward: block0 edge (paths 0,1,2) ----------------
__global__ void k_edge_fwd0(const int* __restrict__ ei,
                            const float* __restrict__ Wr, const float* __restrict__ br) {
    __shared__ float Wrs[640], brs[80];
    for (int i = threadIdx.x; i < 640; i += blockDim.x) Wrs[i] = Wr[i];
    for (int i = threadIdx.x; i < 80;  i += blockDim.x) brs[i] = br[i];
    __syncthreads();
    long t = (long)blockIdx.x * blockDim.x + threadIdx.x;
    int e = (int)(t >> 4), c = (int)(t & 15);
    int rw = ei[e], cl = ei[NE + e];
    float4 g = g_geo[e];
    float s1[3], s2[5];
    sh_basis_f(g.x, g.y, g.z, s1, s2);
    float rad[8];
    #pragma unroll
    for (int n = 0; n < 8; n++) rad[n] = g_radial[e*8 + n];
    float w0 = brs[c], w1 = brs[16 + c], w2 = brs[32 + c];
    #pragma unroll
    for (int n = 0; n < 8; n++) {
        w0 += rad[n] * Wrs[n*80 + c];
        w1 += rad[n] * Wrs[n*80 + 16 + c];
        w2 += rad[n] * Wrs[n*80 + 32 + c];
    }
    float h0c = g_h00[cl*16 + c];
    atomicAdd(&g_a00[rw*16 + c], w0 * h0c);
    float f1 = w1 * h0c, f2 = w2 * h0c;
    #pragma unroll
    for (int m = 0; m < 3; m++) atomicAdd(&g_a10[rw*48 + c*3 + m], f1 * s1[m]);
    #pragma unroll
    for (int m = 0; m < 5; m++) atomicAdd(&g_a20[rw*80 + c*5 + m], f2 * s2[m]);
}

// ---------------- forward: block0 node update ----------------
__global__ void k_node_upd0(const float* __restrict__ Wout) {
    __shared__ float W0s[256], W1s[256], W2s[256];
    for (int i = threadIdx.x; i < 256; i += blockDim.x) {
        W0s[i] = Wout[i]; W1s[i] = Wout[256 + i]; W2s[i] = Wout[512 + i];
    }
    __syncthreads();
    int t = blockIdx.x * blockDim.x + threadIdx.x;
    if (t >= NN * 16) return;
    int n = t >> 4, d = t & 15;
    float acc0 = g_h00[n*16 + d];
    float a1[3] = {0,0,0}, a2[5] = {0,0,0,0,0};
    #pragma unroll
    for (int cc = 0; cc < 16; cc++) {
        acc0 += g_a00[n*16 + cc] * W0s[cc*16 + d];
        float w1 = W1s[cc*16 + d];
        #pragma unroll
        for (int m = 0; m < 3; m++) a1[m] += g_a10[n*48 + cc*3 + m] * w1;
        float w2 = W2s[cc*16 + d];
        #pragma unroll
        for (int m = 0; m < 5; m++) a2[m] += g_a20[n*80 + cc*5 + m] * w2;
    }
    g_h01[n*16 + d] = acc0;
    #pragma unroll
    for (int m = 0; m < 3; m++) g_h11[n*48 + d*3 + m] = a1[m];
    #pragma unroll
    for (int m = 0; m < 5; m++) g_h21[n*80 + d*5 + m] = a2[m];
}

// ---------------- forward: block1 edge (paths 0,3,4; m0 only) ----------------
__global__ void k_edge_fwd1(const int* __restrict__ ei,
                            const float* __restrict__ Wr, const float* __restrict__ br) {
    __shared__ float Wrs[640], brs[80];
    for (int i = threadIdx.x; i < 640; i += blockDim.x) Wrs[i] = Wr[i];
    for (int i = threadIdx.x; i < 80;  i += blockDim.x) brs[i] = br[i];
    __syncthreads();
    long t = (long)blockIdx.x * blockDim.x + threadIdx.x;
    int e = (int)(t >> 4), c = (int)(t & 15);
    int rw = ei[e], cl = ei[NE + e];
    float4 g = g_geo[e];
    float s1[3], s2[5];
    sh_basis_f(g.x, g.y, g.z, s1, s2);
    float rad[8];
    #pragma unroll
    for (int n = 0; n < 8; n++) rad[n] = g_radial[e*8 + n];
    float w0 = brs[c], w3 = brs[48 + c], w4 = brs[64 + c];
    #pragma unroll
    for (int n = 0; n < 8; n++) {
        w0 += rad[n] * Wrs[n*80 + c];
        w3 += rad[n] * Wrs[n*80 + 48 + c];
        w4 += rad[n] * Wrs[n*80 + 64 + c];
    }
    float h0c = g_h01[cl*16 + c];
    float d1 = 0.f, d2 = 0.f;
    #pragma unroll
    for (int m = 0; m < 3; m++) d1 += g_h11[cl*48 + c*3 + m] * s1[m];
    #pragma unroll
    for (int m = 0; m < 5; m++) d2 += g_h21[cl*80 + c*5 + m] * s2[m];
    atomicAdd(&g_a01[rw*16 + c], w0 * h0c + w3 * d1 + w4 * d2);
}

// ---------------- readout: energy + dE/dh0_final ----------------
__global__ void k_readout(const float* __restrict__ W10, const float* __restrict__ W_read,
                          const float* __restrict__ W1, const float* __restrict__ b1,
                          const float* __restrict__ W2, const float* __restrict__ b2) {
    __shared__ float W10s[256], WRs[256], W1s[256], W2s[16], b1s[16];
    __shared__ float b2s;
    __shared__ double esum[256];
    for (int i = threadIdx.x; i < 256; i += blockDim.x) {
        W10s[i] = W10[i]; WRs[i] = W_read[i]; W1s[i] = W1[i];
    }
    if (threadIdx.x < 16) { W2s[threadIdx.x] = W2[threadIdx.x]; b1s[threadIdx.x] = b1[threadIdx.x]; }
    if (threadIdx.x == 0) b2s = b2[0];
    __syncthreads();
    int n = blockIdx.x * blockDim.x + threadIdx.x;
    double site = 0.0;
    if (n < NN) {
        float h0f[16];
        #pragma unroll
        for (int d = 0; d < 16; d++) h0f[d] = g_h01[n*16 + d];
        #pragma unroll
        for (int cc = 0; cc < 16; cc++) {
            float a = g_a01[n*16 + cc];
            #pragma unroll
            for (int d = 0; d < 16; d++) h0f[d] += a * W10s[cc*16 + d];
        }
        float invv[16];
        #pragma unroll
        for (int d = 0; d < 16; d++) {
            float acc = 0.f;
            #pragma unroll
            for (int cc = 0; cc < 16; cc++) acc += h0f[cc] * WRs[cc*16 + d];
            invv[d] = acc;
        }
        float sp[16];
        float sacc = b2s;
        #pragma unroll
        for (int k = 0; k < 16; k++) {
            float tt = b1s[k];
            #pragma unroll
            for (int d = 0; d < 16; d++) tt += invv[d] * W1s[d*16 + k];
            float sg = 1.f / (1.f + expf(-tt));
            sacc += tt * sg * W2s[k];
            sp[k] = sg * (1.f + tt * (1.f - sg)) * W2s[k];
        }
        site = (double)sacc;
        float q[16];
        #pragma unroll
        for (int d = 0; d < 16; d++) {
            float acc = 0.f;
            #pragma unroll
            for (int k = 0; k < 16; k++) acc += W1s[d*16 + k] * sp[k];
            q[d] = acc;
        }
        #pragma unroll
        for (int cc = 0; cc < 16; cc++) {
            float acc = 0.f;
            #pragma unroll
            for (int d = 0; d < 16; d++) acc += WRs[cc*16 + d] * q[d];
            g_g0f[n*16 + cc] = acc;
        }
    }
    esum[threadIdx.x] = site;
    __syncthreads();
    for (int s = 128; s > 0; s >>= 1) {
        if (threadIdx.x < s) esum[threadIdx.x] += esum[threadIdx.x + s];
        __syncthreads();
    }
    if (threadIdx.x == 0) atomicAdd(&g_energy, esum[0]);
}

// ---------------- backward: node-level for block1 ----------------
__global__ void k_bwd_node1(const float* __restrict__ W10) {
    __shared__ float Ws[256];
    for (int i = threadIdx.x; i < 256; i += blockDim.x) Ws[i] = W10[i];
    __syncthreads();
    int t = blockIdx.x * blockDim.x + threadIdx.x;
    if (t >= NN * 16) return;
    int n = t >> 4, c = t & 15;
    float acc = 0.f;
    #pragma unroll
    for (int d = 0; d < 16; d++) acc += g_g0f[n*16 + d] * Ws[c*16 + d];
    g_ga01[t] = acc;
    g_g01[t] = g_g0f[t];
}

// ---------------- backward: block1 edge ----------------
__global__ void k_bwd_edge1(const int* __restrict__ ei,
                            const float* __restrict__ Wr, const float* __restrict__ br) {
    __shared__ float Wrs[640], brs[80];
    for (int i = threadIdx.x; i < 640; i += blockDim.x) Wrs[i] = Wr[i];
    for (int i = threadIdx.x; i < 80;  i += blockDim.x) brs[i] = br[i];
    __syncthreads();
    long t = (long)blockIdx.x * blockDim.x + threadIdx.x;
    int e = (int)(t >> 4), c = (int)(t & 15);
    int rw = ei[e], cl = ei[NE + e];
    float4 g = g_geo[e];
    float s1[3], s2[5];
    sh_basis_f(g.x, g.y, g.z, s1, s2);
    float rad[8];
    #pragma unroll
    for (int n = 0; n < 8; n++) rad[n] = g_radial[e*8 + n];
    float w0 = brs[c], w3 = brs[48 + c], w4 = brs[64 + c];
    #pragma unroll
    for (int n = 0; n < 8; n++) {
        w0 += rad[n] * Wrs[n*80 + c];
        w3 += rad[n] * Wrs[n*80 + 48 + c];
        w4 += rad[n] * Wrs[n*80 + 64 + c];
    }
    float gm0 = g_ga01[rw*16 + c];
    float h0c = g_h01[cl*16 + c];
    float h1c[3], h2c[5];
    #pragma unroll
    for (int m = 0; m < 3; m++) h1c[m] = g_h11[cl*48 + c*3 + m];
    #pragma unroll
    for (int m = 0; m < 5; m++) h2c[m] = g_h21[cl*80 + c*5 + m];

    atomicAdd(&g_g01[cl*16 + c], gm0 * w0);
    float gw3 = gm0 * w3, gw4 = gm0 * w4;
    #pragma unroll
    for (int m = 0; m < 3; m++) atomicAdd(&g_g11[cl*48 + c*3 + m], gw3 * s1[m]);
    #pragma unroll
    for (int m = 0; m < 5; m++) atomicAdd(&g_g21[cl*80 + c*5 + m], gw4 * s2[m]);

    float red[16];
    #pragma unroll
    for (int m = 0; m < 3; m++) red[m] = gw3 * h1c[m];
    #pragma unroll
    for (int m = 0; m < 5; m++) red[3 + m] = gw4 * h2c[m];
    float d1 = 0.f, d2 = 0.f;
    #pragma unroll
    for (int m = 0; m < 3; m++) d1 += h1c[m] * s1[m];
    #pragma unroll
    for (int m = 0; m < 5; m++) d2 += h2c[m] * s2[m];
    float dw0 = gm0 * h0c, dw3 = gm0 * d1, dw4 = gm0 * d2;
    #pragma unroll
    for (int n = 0; n < 8; n++)
        red[8 + n] = dw0 * Wrs[n*80 + c] + dw3 * Wrs[n*80 + 48 + c] + dw4 * Wrs[n*80 + 64 + c];

    #pragma unroll
    for (int off = 8; off > 0; off >>= 1) {
        #pragma unroll
        for (int i = 0; i < 16; i++)
            red[i] += __shfl_xor_sync(0xffffffffu, red[i], off, 16);
    }
    if (c == 0) {
        #pragma unroll
        for (int i = 0; i < 8; i++) g_gsh[e*8 + i] = red[i];
        #pragma unroll
        for (int n = 0; n < 8; n++) g_grad[e*8 + n] = red[8 + n];
    }
}

// ---------------- backward: node-level for block0 ----------------
__global__ void k_bwd_node0(const float* __restrict__ Wout) {
    __shared__ float W0s[256], W1s[256], W2s[256];
    for (int i = threadIdx.x; i < 256; i += blockDim.x) {
        W0s[i] = Wout[i]; W1s[i] = Wout[256 + i]; W2s[i] = Wout[512 + i];
    }
    __syncthreads();
    int t = blockIdx.x * blockDim.x + threadIdx.x;
    if (t >= NN * 16) return;
    int n = t >> 4, c = t & 15;
    float a0 = 0.f, a1[3] = {0,0,0}, a2[5] = {0,0,0,0,0};
    #pragma unroll
    for (int d = 0; d < 16; d++) {
        a0 += g_g01[n*16 + d] * W0s[c*16 + d];
        float w1 = W1s[c*16 + d];
        #pragma unroll
        for (int m = 0; m < 3; m++) a1[m] += g_g11[n*48 + d*3 + m] * w1;
        float w2 = W2s[c*16 + d];
        #pragma unroll
        for (int m = 0; m < 5; m++) a2[m] += g_g21[n*80 + d*5 + m] * w2;
    }
    g_ga00[n*16 + c] = a0;
    #pragma unroll
    for (int m = 0; m < 3; m++) g_ga10[n*48 + c*3 + m] = a1[m];
    #pragma unroll
    for (int m = 0; m < 5; m++) g_ga20[n*80 + c*5 + m] = a2[m];
}

// ---------------- backward: block0 edge + fused gv ----------------
__global__ void k_bwd_edge0(const int* __restrict__ ei,
                            const float* __restrict__ Wr, const float* __restrict__ br) {
    __shared__ float Wrs[640], brs[80];
    for (int i = threadIdx.x; i < 640; i += blockDim.x) Wrs[i] = Wr[i];
    for (int i = threadIdx.x; i < 80;  i += blockDim.x) brs[i] = br[i];
    __syncthreads();
    long t = (long)blockIdx.x * blockDim.x + threadIdx.x;
    int e = (int)(t >> 4), c = (int)(t & 15);
    int rw = ei[e], cl = ei[NE + e];
    float4 g = g_geo[e];
    float s1[3], s2[5];
    sh_basis_f(g.x, g.y, g.z, s1, s2);
    float rad[8];
    #pragma unroll
    for (int n = 0; n < 8; n++) rad[n] = g_radial[e*8 + n];
    float w0 = brs[c], w1 = brs[16 + c], w2 = brs[32 + c];
    #pragma unroll
    for (int n = 0; n < 8; n++) {
        w0 += rad[n] * Wrs[n*80 + c];
        w1 += rad[n] * Wrs[n*80 + 16 + c];
        w2 += rad[n] * Wrs[n*80 + 32 + c];
    }
    float gm0 = g_ga00[rw*16 + c];
    float gm1[3], gm2[5];
    #pragma unroll
    for (int m = 0; m < 3; m++) gm1[m] = g_ga10[rw*48 + c*3 + m];
    #pragma unroll
    for (int m = 0; m < 5; m++) gm2[m] = g_ga20[rw*80 + c*5 + m];
    float h0c = g_h00[cl*16 + c];
    float d1 = 0.f, d2 = 0.f;
    #pragma unroll
    for (int m = 0; m < 3; m++) d1 += gm1[m] * s1[m];
    #pragma unroll
    for (int m = 0; m < 5; m++) d2 += gm2[m] * s2[m];

    float red[16];
    float w1h = w1 * h0c, w2h = w2 * h0c;
    #pragma unroll
    for (int m = 0; m < 3; m++) red[m] = gm1[m] * w1h;
    #pragma unroll
    for (int m = 0; m < 5; m++) red[3 + m] = gm2[m] * w2h;
    float dw0 = gm0 * h0c, dw1 = h0c * d1, dw2 = h0c * d2;
    #pragma unroll
    for (int n = 0; n < 8; n++)
        red[8 + n] = dw0 * Wrs[n*80 + c] + dw1 * Wrs[n*80 + 16 + c] + dw2 * Wrs[n*80 + 32 + c];

    #pragma unroll
    for (int off = 8; off > 0; off >>= 1) {
        #pragma unroll
        for (int i = 0; i < 16; i++)
            red[i] += __shfl_xor_sync(0xffffffffu, red[i], off, 16);
    }
    if (c == 0) {
        // totals: block1 stored + block0 just reduced
        float gs[8], gd[8];
        #pragma unroll
        for (int i = 0; i < 8; i++) gs[i] = g_gsh[e*8 + i] + red[i];
        #pragma unroll
        for (int n = 0; n < 8; n++) gd[n] = g_grad[e*8 + n] + red[8 + n];
        // fused gv = dE/d(edge_vec)
        float ux = g.x, uy = g.y, uz = g.z, r = g.w, inv = 1.f / r;
        const float SQ3 = 1.7320508075688772f;
        const float S15 = 3.872983346207417f;
        const float S5  = 2.23606797749979f;
        const float A   = 0.6324555320336759f;
        const float KPI = 0.6283185307179586f;
        float gux = SQ3 * gs[0] + S15 * (uy * gs[3] + uz * gs[6] + ux * gs[7]);
        float guy = SQ3 * gs[1] + S15 * (ux * gs[3] + uz * gs[4] - uy * gs[7]);
        float guz = SQ3 * gs[2] + S15 * (uy * gs[4] + ux * gs[6]) + 3.f * S5 * uz * gs[5];
        float gr = 0.f;
        #pragma unroll
        for (int n = 0; n < 8; n++) {
            float kn = (float)(n + 1) * KPI;
            // d/dr [A sin(kr)/r] = A*k*cos(kr)/r - radial/r
            gr += gd[n] * (A * kn * cosf(kn * r) - rad[n]) * inv;
        }
        float guu = gux * ux + guy * uy + guz * uz;
        g_gv[e*3 + 0] = gr * ux + (gux - guu * ux) * inv;
        g_gv[e*3 + 1] = gr * uy + (guy - guu * uy) * inv;
        g_gv[e*3 + 2] = gr * uz + (guz - guu * uz) * inv;
    }
}

// ---------------- forces: emulate XLA's two sequential fp32 scatter-adds ----------------
__global__ void k_forces(float* __restrict__ out) {
    int n = blockIdx.x * blockDim.x + threadIdx.x;
    if (n >= NN) return;
    if (n == 0) out[0] = (float)g_energy;
    float a1x = 0.f, a1y = 0.f, a1z = 0.f;
    {
        int lo = g_offR[n], hi = lo + g_cntR[n];
        for (int i = lo; i < hi; i++) {
            int e = g_lstR[i];
            a1x += g_gv[e*3 + 0];
            a1y += g_gv[e*3 + 1];
            a1z += g_gv[e*3 + 2];
        }
    }
    float a2x = 0.f, a2y = 0.f, a2z = 0.f;
    {
        int lo = g_offC[n], hi = lo + g_cntC[n];
        for (int i = lo; i < hi; i++) {
            int e = g_lstC[i];
            a2x += -g_gv[e*3 + 0];
            a2y += -g_gv[e*3 + 1];
            a2z += -g_gv[e*3 + 2];
        }
    }
    out[1 + n*3 + 0] = -(a1x + a2x);
    out[1 + n*3 + 1] = -(a1y + a2y);
    out[1 + n*3 + 2] = -(a1z + a2z);
}

// ---------------- host ----------------
extern "C" void kernel_launch(void* const* d_in, const int* in_sizes, int n_in,
                              void* d_out, int out_size) {
    const float* pos    = (const float*)d_in[0];
    const int*   z      = (const int*)  d_in[1];
    const int*   ei     = (const int*)  d_in[2];
    const float* emb    = (const float*)d_in[3];
    const float* W_init = (const float*)d_in[4];
    const float* Wr     = (const float*)d_in[5];
    const float* br     = (const float*)d_in[6];
    const float* W_out  = (const float*)d_in[7];
    const float* W_read = (const float*)d_in[8];
    const float* W1     = (const float*)d_in[9];
    const float* b1     = (const float*)d_in[10];
    const float* W2     = (const float*)d_in[11];
    const float* b2     = (const float*)d_in[12];
    float* out = (float*)d_out;

    void *pa00, *pa10, *pa20, *pa01, *pg11, *pg21, *pen;
    void *pcr, *pcc, *pur, *puc, *por, *poc;
    cudaGetSymbolAddress(&pa00, g_a00);
    cudaGetSymbolAddress(&pa10, g_a10);
    cudaGetSymbolAddress(&pa20, g_a20);
    cudaGetSymbolAddress(&pa01, g_a01);
    cudaGetSymbolAddress(&pg11, g_g11);
    cudaGetSymbolAddress(&pg21, g_g21);
    cudaGetSymbolAddress(&pen,  g_energy);
    cudaGetSymbolAddress(&pcr,  g_cntR);
    cudaGetSymbolAddress(&pcc,  g_cntC);
    cudaGetSymbolAddress(&pur,  g_curR);
    cudaGetSymbolAddress(&puc,  g_curC);
    cudaGetSymbolAddress(&por,  g_offR);
    cudaGetSymbolAddress(&poc,  g_offC);

    cudaMemsetAsync(pa00, 0, sizeof(float) * NN * 16, 0);
    cudaMemsetAsync(pa10, 0, sizeof(float) * NN * 48, 0);
    cudaMemsetAsync(pa20, 0, sizeof(float) * NN * 80, 0);
    cudaMemsetAsync(pa01, 0, sizeof(float) * NN * 16, 0);
    cudaMemsetAsync(pg11, 0, sizeof(float) * NN * 48, 0);
    cudaMemsetAsync(pg21, 0, sizeof(float) * NN * 80, 0);
    cudaMemsetAsync(pen,  0, sizeof(double), 0);
    cudaMemsetAsync(pcr,  0, sizeof(int) * NN, 0);
    cudaMemsetAsync(pcc,  0, sizeof(int) * NN, 0);
    cudaMemsetAsync(pur,  0, sizeof(int) * NN, 0);
    cudaMemsetAsync(puc,  0, sizeof(int) * NN, 0);

    const int TPB = 256;
    k_geom_fwd <<<NE / TPB, TPB>>>(pos, ei);
    k_scan     <<<1, 1024>>>((const int*)pcr, (int*)por);
    k_scan     <<<1, 1024>>>((const int*)pcc, (int*)poc);
    k_fill     <<<NE / TPB, TPB>>>(ei);
    k_sort     <<<(NN + TPB - 1) / TPB, TPB>>>();
    k_node_init<<<NN * 16 / TPB, TPB>>>(emb, z, W_init);
    k_edge_fwd0<<<NE * 16 / TPB, TPB>>>(ei, Wr, br);
    k_node_upd0<<<NN * 16 / TPB, TPB>>>(W_out);
    k_edge_fwd1<<<NE * 16 / TPB, TPB>>>(ei, Wr + 640, br + 80);
    k_readout  <<<(NN + TPB - 1) / TPB, TPB>>>(W_out + 768, W_read, W1, b1, W2, b2);
    k_bwd_node1<<<NN * 16 / TPB, TPB>>>(W_out + 768);
    k_bwd_edge1<<<NE * 16 / TPB, TPB>>>(ei, Wr + 640, br + 80);
    k_bwd_node0<<<NN * 16 / TPB, TPB>>>(W_out);
    k_bwd_edge0<<<NE * 16 / TPB, TPB>>>(ei, Wr, br);
    k_forces   <<<(NN + TPB - 1) / TPB, TPB>>>(out);
}

// round 7
// speedup vs baseline: 8.9262x; 1.1263x over previous
#include <cuda_runtime.h>
#include <math.h>

#define NE 480000
#define NN 30000

// ---------------- scratch (device globals; no allocation) ----------------
static __device__ float4 g_geo[NE];          // ux,uy,uz,r
static __device__ float  g_radial[NE*8];
static __device__ float  g_h00[NN*16];
static __device__ float  g_a00[NN*16];
static __device__ float  g_a10[NN*48];
static __device__ float  g_a20[NN*80];
static __device__ float  g_h01[NN*16];
static __device__ float  g_h11[NN*48];
static __device__ float  g_h21[NN*80];
static __device__ float  g_a01[NN*16];
static __device__ float  g_g0f[NN*16];
static __device__ float  g_ga01[NN*16];
static __device__ float  g_g01[NN*16];
static __device__ float  g_g11[NN*48];
static __device__ float  g_g21[NN*80];
static __device__ float  g_ga00[NN*16];
static __device__ float  g_ga10[NN*48];
static __device__ float  g_ga20[NN*80];
static __device__ float  g_gsh[NE*8];        // block1 edge: [0..2]=dsh1, [3..7]=dsh2
static __device__ float  g_grad[NE*8];       // block1 edge: dE/dradial
static __device__ double g_energy;
// ---- CSR (row and col) ----
static __device__ int    g_cntR[NN], g_cntC[NN];
static __device__ int    g_offR[NN], g_offC[NN];
static __device__ int    g_curR[NN], g_curC[NN];
static __device__ int    g_lstR[NE], g_lstC[NE];
static __device__ float  g_gv[NE*3];         // per-edge dE/d(edge_vec), fp32

__device__ __forceinline__ void sh_basis_f(float ux, float uy, float uz,
                                           float* s1, float* s2) {
    const float SQ3 = 1.7320508075688772f;
    const float S15 = 3.872983346207417f;
    const float S5  = 2.23606797749979f;
    s1[0] = SQ3 * ux; s1[1] = SQ3 * uy; s1[2] = SQ3 * uz;
    s2[0] = S15 * ux * uy;
    s2[1] = S15 * uy * uz;
    s2[2] = 0.5f * S5 * (3.f * uz * uz - 1.f);
    s2[3] = S15 * ux * uz;
    s2[4] = 0.5f * S15 * (ux * ux - uy * uy);
}

// ---------------- forward: geometry (+ CSR counting) ----------------
__global__ void k_geom_fwd(const float* __restrict__ pos, const int* __restrict__ ei) {
    int e = blockIdx.x * blockDim.x + threadIdx.x;
    if (e >= NE) return;
    int rw = ei[e], cl = ei[NE + e];
    float vx = pos[3*rw+0] - pos[3*cl+0];
    float vy = pos[3*rw+1] - pos[3*cl+1];
    float vz = pos[3*rw+2] - pos[3*cl+2];
    float r = sqrtf(vx*vx + vy*vy + vz*vz + 1e-12f);
    float inv = 1.f / r;
    g_geo[e] = make_float4(vx*inv, vy*inv, vz*inv, r);
    const float A = 0.6324555320336759f;       // sqrt(2/5)
    const float KPI = 0.6283185307179586f;     // pi/5
    #pragma unroll
    for (int n = 0; n < 8; n++) {
        float kn = (float)(n + 1) * KPI;
        g_radial[e*8 + n] = A * sinf(kn * r) * inv;
    }
    atomicAdd(&g_cntR[rw], 1);
    atomicAdd(&g_cntC[cl], 1);
}

// ---------------- CSR: exclusive scan (single block, 1024 threads) ----------------
__global__ void k_scan(const int* __restrict__ cnt, int* __restrict__ off) {
    __shared__ int part[1024];
    const int CH = 32;
    int t = threadIdx.x;
    int base = t * CH;
    int s = 0;
    for (int i = 0; i < CH; i++) {
        int idx = base + i;
        if (idx < NN) s += cnt[idx];
    }
    part[t] = s;
    __syncthreads();
    for (int o = 1; o < 1024; o <<= 1) {
        int v = (t >= o) ? part[t - o] : 0;
        __syncthreads();
        part[t] += v;
        __syncthreads();
    }
    int run = (t > 0) ? part[t - 1] : 0;
    for (int i = 0; i < CH; i++) {
        int idx = base + i;
        if (idx < NN) { off[idx] = run; run += cnt[idx]; }
    }
}

// ---------------- CSR: fill (unordered) ----------------
__global__ void k_fill(const int* __restrict__ ei) {
    int e = blockIdx.x * blockDim.x + threadIdx.x;
    if (e >= NE) return;
    int rw = ei[e], cl = ei[NE + e];
    int p1 = g_offR[rw] + atomicAdd(&g_curR[rw], 1);
    g_lstR[p1] = e;
    int p2 = g_offC[cl] + atomicAdd(&g_curC[cl], 1);
    g_lstC[p2] = e;
}

// ---------------- CSR: sort each bucket ascending ----------------
__global__ void k_sort() {
    int n = blockIdx.x * blockDim.x + threadIdx.x;
    if (n >= NN) return;
    {
        int lo = g_offR[n], hi = lo + g_cntR[n];
        for (int i = lo + 1; i < hi; i++) {
            int key = g_lstR[i], j = i - 1;
            while (j >= lo && g_lstR[j] > key) { g_lstR[j+1] = g_lstR[j]; j--; }
            g_lstR[j+1] = key;
        }
    }
    {
        int lo = g_offC[n], hi = lo + g_cntC[n];
        for (int i = lo + 1; i < hi; i++) {
            int key = g_lstC[i], j = i - 1;
            while (j >= lo && g_lstC[j] > key) { g_lstC[j+1] = g_lstC[j]; j--; }
            g_lstC[j+1] = key;
        }
    }
}

// ---------------- forward: h0 init = emb[z] @ W_init ----------------
__global__ void k_node_init(const float* __restrict__ emb, const int* __restrict__ z,
                            const float* __restrict__ W_init) {
    __shared__ float Ws[256];
    for (int i = threadIdx.x; i < 256; i += blockDim.x) Ws[i] = W_init[i];
    __syncthreads();
    int t = blockIdx.x * blockDim.x + threadIdx.x;
    if (t >= NN * 16) return;
    int n = t >> 4, d = t & 15;
    const float* er = emb + z[n] * 16;
    float acc = 0.f;
    #pragma unroll
    for (int k = 0; k < 16; k++) acc += er[k] * Ws[k*16 + d];
    g_h00[t] = acc;
}

// ---------------- forward: block0 gather (row-CSR; no atomics) ----------------
__global__ void k_gath_fwd0(const int* __restrict__ ei,
                            const float* __restrict__ Wr, const float* __restrict__ br) {
    __shared__ float Wrs[640], brs[80];
    for (int i = threadIdx.x; i < 640; i += blockDim.x) Wrs[i] = Wr[i];
    for (int i = threadIdx.x; i < 80;  i += blockDim.x) brs[i] = br[i];
    __syncthreads();
    int t = blockIdx.x * blockDim.x + threadIdx.x;
    int n = t >> 4, c = t & 15;
    float w0b = brs[c], w1b = brs[16 + c], w2b = brs[32 + c];
    float acc0 = 0.f, a1[3] = {0,0,0}, a2[5] = {0,0,0,0,0};
    int lo = g_offR[n], hi = lo + g_cntR[n];
    for (int i = lo; i < hi; i++) {
        int e = g_lstR[i];
        int cl = ei[NE + e];
        float4 g = g_geo[e];
        float s1[3], s2[5];
        sh_basis_f(g.x, g.y, g.z, s1, s2);
        float w0 = w0b, w1 = w1b, w2 = w2b;
        #pragma unroll
        for (int k = 0; k < 8; k++) {
            float rad = g_radial[e*8 + k];
            w0 += rad * Wrs[k*80 + c];
            w1 += rad * Wrs[k*80 + 16 + c];
            w2 += rad * Wrs[k*80 + 32 + c];
        }
        float h0c = g_h00[cl*16 + c];
        acc0 += w0 * h0c;
        float f1 = w1 * h0c, f2 = w2 * h0c;
        #pragma unroll
        for (int m = 0; m < 3; m++) a1[m] += f1 * s1[m];
        #pragma unroll
        for (int m = 0; m < 5; m++) a2[m] += f2 * s2[m];
    }
    g_a00[n*16 + c] = acc0;
    #pragma unroll
    for (int m = 0; m < 3; m++) g_a10[n*48 + c*3 + m] = a1[m];
    #pragma unroll
    for (int m = 0; m < 5; m++) g_a20[n*80 + c*5 + m] = a2[m];
}

// ---------------- forward: block0 node update ----------------
__global__ void k_node_upd0(const float* __restrict__ Wout) {
    __shared__ float W0s[256], W1s[256], W2s[256];
    for (int i = threadIdx.x; i < 256; i += blockDim.x) {
        W0s[i] = Wout[i]; W1s[i] = Wout[256 + i]; W2s[i] = Wout[512 + i];
    }
    __syncthreads();
    int t = blockIdx.x * blockDim.x + threadIdx.x;
    if (t >= NN * 16) return;
    int n = t >> 4, d = t & 15;
    float acc0 = g_h00[n*16 + d];
    float a1[3] = {0,0,0}, a2[5] = {0,0,0,0,0};
    #pragma unroll
    for (int cc = 0; cc < 16; cc++) {
        acc0 += g_a00[n*16 + cc] * W0s[cc*16 + d];
        float w1 = W1s[cc*16 + d];
        #pragma unroll
        for (int m = 0; m < 3; m++) a1[m] += g_a10[n*48 + cc*3 + m] * w1;
        float w2 = W2s[cc*16 + d];
        #pragma unroll
        for (int m = 0; m < 5; m++) a2[m] += g_a20[n*80 + cc*5 + m] * w2;
    }
    g_h01[n*16 + d] = acc0;
    #pragma unroll
    for (int m = 0; m < 3; m++) g_h11[n*48 + d*3 + m] = a1[m];
    #pragma unroll
    for (int m = 0; m < 5; m++) g_h21[n*80 + d*5 + m] = a2[m];
}

// ---------------- forward: block1 gather (row-CSR; m0 only) ----------------
__global__ void k_gath_fwd1(const int* __restrict__ ei,
                            const float* __restrict__ Wr, const float* __restrict__ br) {
    __shared__ float Wrs[640], brs[80];
    for (int i = threadIdx.x; i < 640; i += blockDim.x) Wrs[i] = Wr[i];
    for (int i = threadIdx.x; i < 80;  i += blockDim.x) brs[i] = br[i];
    __syncthreads();
    int t = blockIdx.x * blockDim.x + threadIdx.x;
    int n = t >> 4, c = t & 15;
    float w0b = brs[c], w3b = brs[48 + c], w4b = brs[64 + c];
    float acc = 0.f;
    int lo = g_offR[n], hi = lo + g_cntR[n];
    for (int i = lo; i < hi; i++) {
        int e = g_lstR[i];
        int cl = ei[NE + e];
        float4 g = g_geo[e];
        float s1[3], s2[5];
        sh_basis_f(g.x, g.y, g.z, s1, s2);
        float w0 = w0b, w3 = w3b, w4 = w4b;
        #pragma unroll
        for (int k = 0; k < 8; k++) {
            float rad = g_radial[e*8 + k];
            w0 += rad * Wrs[k*80 + c];
            w3 += rad * Wrs[k*80 + 48 + c];
            w4 += rad * Wrs[k*80 + 64 + c];
        }
        float h0c = g_h01[cl*16 + c];
        float d1 = 0.f, d2 = 0.f;
        #pragma unroll
        for (int m = 0; m < 3; m++) d1 += g_h11[cl*48 + c*3 + m] * s1[m];
        #pragma unroll
        for (int m = 0; m < 5; m++) d2 += g_h21[cl*80 + c*5 + m] * s2[m];
        acc += w0 * h0c + w3 * d1 + w4 * d2;
    }
    g_a01[n*16 + c] = acc;
}

// ---------------- readout: energy + g0f + ga01 (fused bwd_node1) ----------------
__global__ void k_readout(const float* __restrict__ W10, const float* __restrict__ W_read,
                          const float* __restrict__ W1, const float* __restrict__ b1,
                          const float* __restrict__ W2, const float* __restrict__ b2) {
    __shared__ float W10s[256], WRs[256], W1s[256], W2s[16], b1s[16];
    __shared__ float b2s;
    __shared__ double esum[256];
    for (int i = threadIdx.x; i < 256; i += blockDim.x) {
        W10s[i] = W10[i]; WRs[i] = W_read[i]; W1s[i] = W1[i];
    }
    if (threadIdx.x < 16) { W2s[threadIdx.x] = W2[threadIdx.x]; b1s[threadIdx.x] = b1[threadIdx.x]; }
    if (threadIdx.x == 0) b2s = b2[0];
    __syncthreads();
    int n = blockIdx.x * blockDim.x + threadIdx.x;
    double site = 0.0;
    if (n < NN) {
        float h0f[16];
        #pragma unroll
        for (int d = 0; d < 16; d++) h0f[d] = g_h01[n*16 + d];
        #pragma unroll
        for (int cc = 0; cc < 16; cc++) {
            float a = g_a01[n*16 + cc];
            #pragma unroll
            for (int d = 0; d < 16; d++) h0f[d] += a * W10s[cc*16 + d];
        }
        float invv[16];
        #pragma unroll
        for (int d = 0; d < 16; d++) {
            float acc = 0.f;
            #pragma unroll
            for (int cc = 0; cc < 16; cc++) acc += h0f[cc] * WRs[cc*16 + d];
            invv[d] = acc;
        }
        float sp[16];
        float sacc = b2s;
        #pragma unroll
        for (int k = 0; k < 16; k++) {
            float tt = b1s[k];
            #pragma unroll
            for (int d = 0; d < 16; d++) tt += invv[d] * W1s[d*16 + k];
            float sg = 1.f / (1.f + expf(-tt));
            sacc += tt * sg * W2s[k];
            sp[k] = sg * (1.f + tt * (1.f - sg)) * W2s[k];
        }
        site = (double)sacc;
        float q[16];
        #pragma unroll
        for (int d = 0; d < 16; d++) {
            float acc = 0.f;
            #pragma unroll
            for (int k = 0; k < 16; k++) acc += W1s[d*16 + k] * sp[k];
            q[d] = acc;
        }
        float gg[16];
        #pragma unroll
        for (int cc = 0; cc < 16; cc++) {
            float acc = 0.f;
            #pragma unroll
            for (int d = 0; d < 16; d++) acc += WRs[cc*16 + d] * q[d];
            gg[cc] = acc;
            g_g0f[n*16 + cc] = acc;
        }
        // fused bwd_node1: ga01 = g0f @ W10^T
        #pragma unroll
        for (int c = 0; c < 16; c++) {
            float acc = 0.f;
            #pragma unroll
            for (int d = 0; d < 16; d++) acc += gg[d] * W10s[c*16 + d];
            g_ga01[n*16 + c] = acc;
        }
    }
    esum[threadIdx.x] = site;
    __syncthreads();
    for (int s = 128; s > 0; s >>= 1) {
        if (threadIdx.x < s) esum[threadIdx.x] += esum[threadIdx.x + s];
        __syncthreads();
    }
    if (threadIdx.x == 0) atomicAdd(&g_energy, esum[0]);
}

// ---------------- backward: block1 gather (col-CSR; no atomics) ----------------
__global__ void k_gath_bwd1(const int* __restrict__ ei,
                            const float* __restrict__ Wr, const float* __restrict__ br) {
    __shared__ float Wrs[640], brs[80];
    for (int i = threadIdx.x; i < 640; i += blockDim.x) Wrs[i] = Wr[i];
    for (int i = threadIdx.x; i < 80;  i += blockDim.x) brs[i] = br[i];
    __syncthreads();
    int t = blockIdx.x * blockDim.x + threadIdx.x;
    int n = t >> 4, c = t & 15;
    // 16-lane group mask within the warp
    unsigned gmask = 0xFFFFu << (threadIdx.x & 16);
    float w0b = brs[c], w3b = brs[48 + c], w4b = brs[64 + c];
    // own-node forward activations (scatter target cl == n)
    float h0c = g_h01[n*16 + c];
    float h1c[3], h2c[5];
    #pragma unroll
    for (int m = 0; m < 3; m++) h1c[m] = g_h11[n*48 + c*3 + m];
    #pragma unroll
    for (int m = 0; m < 5; m++) h2c[m] = g_h21[n*80 + c*5 + m];
    float g01acc = g_g0f[n*16 + c];           // identity path
    float g11acc[3] = {0,0,0}, g21acc[5] = {0,0,0,0,0};
    int lo = g_offC[n], hi = lo + g_cntC[n];
    for (int i = lo; i < hi; i++) {
        int e = g_lstC[i];
        int rw = ei[e];
        float4 g = g_geo[e];
        float s1[3], s2[5];
        sh_basis_f(g.x, g.y, g.z, s1, s2);
        float w0 = w0b, w3 = w3b, w4 = w4b;
        #pragma unroll
        for (int k = 0; k < 8; k++) {
            float rad = g_radial[e*8 + k];
            w0 += rad * Wrs[k*80 + c];
            w3 += rad * Wrs[k*80 + 48 + c];
            w4 += rad * Wrs[k*80 + 64 + c];
        }
        float gm0 = g_ga01[rw*16 + c];
        g01acc += gm0 * w0;
        float gw3 = gm0 * w3, gw4 = gm0 * w4;
        #pragma unroll
        for (int m = 0; m < 3; m++) g11acc[m] += gw3 * s1[m];
        #pragma unroll
        for (int m = 0; m < 5; m++) g21acc[m] += gw4 * s2[m];
        // per-edge dsh / dradial (reduce over the 16 channels of this group)
        float red[16];
        #pragma unroll
        for (int m = 0; m < 3; m++) red[m] = gw3 * h1c[m];
        #pragma unroll
        for (int m = 0; m < 5; m++) red[3 + m] = gw4 * h2c[m];
        float d1 = 0.f, d2 = 0.f;
        #pragma unroll
        for (int m = 0; m < 3; m++) d1 += h1c[m] * s1[m];
        #pragma unroll
        for (int m = 0; m < 5; m++) d2 += h2c[m] * s2[m];
        float dw0 = gm0 * h0c, dw3 = gm0 * d1, dw4 = gm0 * d2;
        #pragma unroll
        for (int k = 0; k < 8; k++)
            red[8 + k] = dw0 * Wrs[k*80 + c] + dw3 * Wrs[k*80 + 48 + c]
                       + dw4 * Wrs[k*80 + 64 + c];
        #pragma unroll
        for (int off = 8; off > 0; off >>= 1) {
            #pragma unroll
            for (int j = 0; j < 16; j++)
                red[j] += __shfl_xor_sync(gmask, red[j], off, 16);
        }
        if (c == 0) {
            #pragma unroll
            for (int j = 0; j < 8; j++) g_gsh[e*8 + j] = red[j];
            #pragma unroll
            for (int k = 0; k < 8; k++) g_grad[e*8 + k] = red[8 + k];
        }
    }
    g_g01[n*16 + c] = g01acc;
    #pragma unroll
    for (int m = 0; m < 3; m++) g_g11[n*48 + c*3 + m] = g11acc[m];
    #pragma unroll
    for (int m = 0; m < 5; m++) g_g21[n*80 + c*5 + m] = g21acc[m];
}

// ---------------- backward: node-level for block0 ----------------
__global__ void k_bwd_node0(const float* __restrict__ Wout) {
    __shared__ float W0s[256], W1s[256], W2s[256];
    for (int i = threadIdx.x; i < 256; i += blockDim.x) {
        W0s[i] = Wout[i]; W1s[i] = Wout[256 + i]; W2s[i] = Wout[512 + i];
    }
    __syncthreads();
    int t = blockIdx.x * blockDim.x + threadIdx.x;
    if (t >= NN * 16) return;
    int n = t >> 4, c = t & 15;
    float a0 = 0.f, a1[3] = {0,0,0}, a2[5] = {0,0,0,0,0};
    #pragma unroll
    for (int d = 0; d < 16; d++) {
        a0 += g_g01[n*16 + d] * W0s[c*16 + d];
        float w1 = W1s[c*16 + d];
        #pragma unroll
        for (int m = 0; m < 3; m++) a1[m] += g_g11[n*48 + d*3 + m] * w1;
        float w2 = W2s[c*16 + d];
        #pragma unroll
        for (int m = 0; m < 5; m++) a2[m] += g_g21[n*80 + d*5 + m] * w2;
    }
    g_ga00[n*16 + c] = a0;
    #pragma unroll
    for (int m = 0; m < 3; m++) g_ga10[n*48 + c*3 + m] = a1[m];
    #pragma unroll
    for (int m = 0; m < 5; m++) g_ga20[n*80 + c*5 + m] = a2[m];
}

// ---------------- backward: block0 edge (no atomics) + fused gv ----------------
__global__ void k_bwd_edge0(const int* __restrict__ ei,
                            const float* __restrict__ Wr, const float* __restrict__ br) {
    __shared__ float Wrs[640], brs[80];
    for (int i = threadIdx.x; i < 640; i += blockDim.x) Wrs[i] = Wr[i];
    for (int i = threadIdx.x; i < 80;  i += blockDim.x) brs[i] = br[i];
    __syncthreads();
    long t = (long)blockIdx.x * blockDim.x + threadIdx.x;
    int e = (int)(t >> 4), c = (int)(t & 15);
    int rw = ei[e], cl = ei[NE + e];
    float4 g = g_geo[e];
    float s1[3], s2[5];
    sh_basis_f(g.x, g.y, g.z, s1, s2);
    float rad[8];
    #pragma unroll
    for (int n = 0; n < 8; n++) rad[n] = g_radial[e*8 + n];
    float w0 = brs[c], w1 = brs[16 + c], w2 = brs[32 + c];
    #pragma unroll
    for (int n = 0; n < 8; n++) {
        w0 += rad[n] * Wrs[n*80 + c];
        w1 += rad[n] * Wrs[n*80 + 16 + c];
        w2 += rad[n] * Wrs[n*80 + 32 + c];
    }
    float gm0 = g_ga00[rw*16 + c];
    float gm1[3], gm2[5];
    #pragma unroll
    for (int m = 0; m < 3; m++) gm1[m] = g_ga10[rw*48 + c*3 + m];
    #pragma unroll
    for (int m = 0; m < 5; m++) gm2[m] = g_ga20[rw*80 + c*5 + m];
    float h0c = g_h00[cl*16 + c];
    float d1 = 0.f, d2 = 0.f;
    #pragma unroll
    for (int m = 0; m < 3; m++) d1 += gm1[m] * s1[m];
    #pragma unroll
    for (int m = 0; m < 5; m++) d2 += gm2[m] * s2[m];

    float red[16];
    float w1h = w1 * h0c, w2h = w2 * h0c;
    #pragma unroll
    for (int m = 0; m < 3; m++) red[m] = gm1[m] * w1h;
    #pragma unroll
    for (int m = 0; m < 5; m++) red[3 + m] = gm2[m] * w2h;
    float dw0 = gm0 * h0c, dw1 = h0c * d1, dw2 = h0c * d2;
    #pragma unroll
    for (int n = 0; n < 8; n++)
        red[8 + n] = dw0 * Wrs[n*80 + c] + dw1 * Wrs[n*80 + 16 + c] + dw2 * Wrs[n*80 + 32 + c];

    #pragma unroll
    for (int off = 8; off > 0; off >>= 1) {
        #pragma unroll
        for (int i = 0; i < 16; i++)
            red[i] += __shfl_xor_sync(0xffffffffu, red[i], off, 16);
    }
    if (c == 0) {
        float gs[8], gd[8];
        #pragma unroll
        for (int i = 0; i < 8; i++) gs[i] = g_gsh[e*8 + i] + red[i];
        #pragma unroll
        for (int n = 0; n < 8; n++) gd[n] = g_grad[e*8 + n] + red[8 + n];
        float ux = g.x, uy = g.y, uz = g.z, r = g.w, inv = 1.f / r;
        const float SQ3 = 1.7320508075688772f;
        const float S15 = 3.872983346207417f;
        const float S5  = 2.23606797749979f;
        const float A   = 0.6324555320336759f;
        const float KPI = 0.6283185307179586f;
        float gux = SQ3 * gs[0] + S15 * (uy * gs[3] + uz * gs[6] + ux * gs[7]);
        float guy = SQ3 * gs[1] + S15 * (ux * gs[3] + uz * gs[4] - uy * gs[7]);
        float guz = SQ3 * gs[2] + S15 * (uy * gs[4] + ux * gs[6]) + 3.f * S5 * uz * gs[5];
        float gr = 0.f;
        #pragma unroll
        for (int n = 0; n < 8; n++) {
            float kn = (float)(n + 1) * KPI;
            gr += gd[n] * (A * kn * cosf(kn * r) - rad[n]) * inv;
        }
        float guu = gux * ux + guy * uy + guz * uz;
        g_gv[e*3 + 0] = gr * ux + (gux - guu * ux) * inv;
        g_gv[e*3 + 1] = gr * uy + (guy - guu * uy) * inv;
        g_gv[e*3 + 2] = gr * uz + (guz - guu * uz) * inv;
    }
}

// ---------------- forces: emulate XLA's two sequential fp32 scatter-adds ----------------
__global__ void k_forces(float* __restrict__ out) {
    int n = blockIdx.x * blockDim.x + threadIdx.x;
    if (n >= NN) return;
    if (n == 0) out[0] = (float)g_energy;
    float a1x = 0.f, a1y = 0.f, a1z = 0.f;
    {
        int lo = g_offR[n], hi = lo + g_cntR[n];
        for (int i = lo; i < hi; i++) {
            int e = g_lstR[i];
            a1x += g_gv[e*3 + 0];
            a1y += g_gv[e*3 + 1];
            a1z += g_gv[e*3 + 2];
        }
    }
    float a2x = 0.f, a2y = 0.f, a2z = 0.f;
    {
        int lo = g_offC[n], hi = lo + g_cntC[n];
        for (int i = lo; i < hi; i++) {
            int e = g_lstC[i];
            a2x += -g_gv[e*3 + 0];
            a2y += -g_gv[e*3 + 1];
            a2z += -g_gv[e*3 + 2];
        }
    }
    out[1 + n*3 + 0] = -(a1x + a2x);
    out[1 + n*3 + 1] = -(a1y + a2y);
    out[1 + n*3 + 2] = -(a1z + a2z);
}

// ---------------- host ----------------
extern "C" void kernel_launch(void* const* d_in, const int* in_sizes, int n_in,
                              void* d_out, int out_size) {
    const float* pos    = (const float*)d_in[0];
    const int*   z      = (const int*)  d_in[1];
    const int*   ei     = (const int*)  d_in[2];
    const float* emb    = (const float*)d_in[3];
    const float* W_init = (const float*)d_in[4];
    const float* Wr     = (const float*)d_in[5];
    const float* br     = (const float*)d_in[6];
    const float* W_out  = (const float*)d_in[7];
    const float* W_read = (const float*)d_in[8];
    const float* W1     = (const float*)d_in[9];
    const float* b1     = (const float*)d_in[10];
    const float* W2     = (const float*)d_in[11];
    const float* b2     = (const float*)d_in[12];
    float* out = (float*)d_out;

    void *pen, *pcr, *pcc, *pur, *puc, *por, *poc;
    cudaGetSymbolAddress(&pen, g_energy);
    cudaGetSymbolAddress(&pcr, g_cntR);
    cudaGetSymbolAddress(&pcc, g_cntC);
    cudaGetSymbolAddress(&pur, g_curR);
    cudaGetSymbolAddress(&puc, g_curC);
    cudaGetSymbolAddress(&por, g_offR);
    cudaGetSymbolAddress(&poc, g_offC);

    cudaMemsetAsync(pen, 0, sizeof(double), 0);
    cudaMemsetAsync(pcr, 0, sizeof(int) * NN, 0);
    cudaMemsetAsync(pcc, 0, sizeof(int) * NN, 0);
    cudaMemsetAsync(pur, 0, sizeof(int) * NN, 0);
    cudaMemsetAsync(puc, 0, sizeof(int) * NN, 0);

    const int TPB = 256;
    k_geom_fwd <<<NE / TPB, TPB>>>(pos, ei);
    k_scan     <<<1, 1024>>>((const int*)pcr, (int*)por);
    k_scan     <<<1, 1024>>>((const int*)pcc, (int*)poc);
    k_fill     <<<NE / TPB, TPB>>>(ei);
    k_sort     <<<(NN + TPB - 1) / TPB, TPB>>>();
    k_node_init<<<NN * 16 / TPB, TPB>>>(emb, z, W_init);
    k_gath_fwd0<<<NN * 16 / TPB, TPB>>>(ei, Wr, br);
    k_node_upd0<<<NN * 16 / TPB, TPB>>>(W_out);
    k_gath_fwd1<<<NN * 16 / TPB, TPB>>>(ei, Wr + 640, br + 80);
    k_readout  <<<(NN + TPB - 1) / TPB, TPB>>>(W_out + 768, W_read, W1, b1, W2, b2);
    k_gath_bwd1<<<NN * 16 / TPB, TPB>>>(ei, Wr + 640, br + 80);
    k_bwd_node0<<<NN * 16 / TPB, TPB>>>(W_out);
    k_bwd_edge0<<<NE * 16 / TPB, TPB>>>(ei, Wr, br);
    k_forces   <<<(NN + TPB - 1) / TPB, TPB>>>(out);
}